// round 1
// baseline (speedup 1.0000x reference)
#include <cuda_runtime.h>
#include <math.h>

#define HDIM 512
#define NN2 32
#define LEN 2048
#define MM (LEN/2 + 1)   // 1025

#ifndef PI_D
#define PI_D 3.14159265358979323846
#endif

// scratch: half-spectrum k_f per h (complex)
__device__ float2 g_kf[HDIM * MM];

// ---------------------------------------------------------------------------
// Stage 1: Cauchy kernel + rank-1 Woodbury + bilinear post-factor.
// z_m = 2i*tan(pi*m/L)  (purely imaginary);  2/(1+omega) = 1 + i*tan(pi*m/L)
// ---------------------------------------------------------------------------
__global__ void __launch_bounds__(128)
cauchy_kernel(const float* __restrict__ log_dt,
              const float* __restrict__ log_w_real,
              const float* __restrict__ w_imag,
              const float* __restrict__ Bmat,
              const float* __restrict__ Cmat,
              const float* __restrict__ Pmat)
{
    __shared__ float2 sw[NN2];
    __shared__ float2 sv0[NN2], sv1[NN2], sv2[NN2], sv3[NN2];
    __shared__ float  s_dt;

    const int h   = blockIdx.x;
    const int tid = threadIdx.x;

    if (tid < NN2) {
        const int n   = tid;
        const int idx = h * NN2 + n;
        const float dt = expf(log_dt[h]);
        const float wr = -expf(log_w_real[idx]) * dt;
        const float wi = w_imag[idx] * dt;
        sw[n] = make_float2(wr, wi);

        const float Br = Bmat[idx*2],  Bi = Bmat[idx*2+1];
        const float Cr = Cmat[idx*2],  Ci = Cmat[idx*2+1];
        const float Pr = Pmat[idx*2],  Pi = Pmat[idx*2+1];
        // v00 = B*C ; v01 = B*conj(P) ; v10 = P*C ; v11 = |P|^2 (real)
        sv0[n] = make_float2(Br*Cr - Bi*Ci, Br*Ci + Bi*Cr);
        sv1[n] = make_float2(Br*Pr + Bi*Pi, Bi*Pr - Br*Pi);
        sv2[n] = make_float2(Pr*Cr - Pi*Ci, Pr*Ci + Pi*Cr);
        sv3[n] = make_float2(Pr*Pr + Pi*Pi, 0.f);
        if (n == 0) s_dt = dt;
    }
    __syncthreads();

    const int m = blockIdx.y * blockDim.x + tid;
    if (m >= MM) return;

    // tan(pi*m/L) in double: handles the m=1024 pole (tan(pi/2_dbl) ~ 1.6e16);
    // huge z and huge (1+i*t) cancel to the analytic Nyquist limit.
    const double ang = (double)m * (PI_D / (double)LEN);
    const float  tf  = (float)tan(ang);
    const float  z2  = 2.0f * tf;          // Im(z_m)

    float aR0 = 0.f, aI0 = 0.f;  // B*C
    float aR1 = 0.f, aI1 = 0.f;  // B*Q
    float aR2 = 0.f, aI2 = 0.f;  // P*C
    float aR3 = 0.f, aI3 = 0.f;  // P*Q

    #pragma unroll 8
    for (int n = 0; n < NN2; n++) {
        const float2 w = sw[n];
        const float wr2 = w.x * w.x;
        const float u1  = z2 - w.y;        // Im(z - w)
        const float u2  = z2 + w.y;        // Im(z - conj(w))
        const float r1  = __fdividef(1.0f, wr2 + u1*u1);
        const float r2  = __fdividef(1.0f, wr2 + u2*u2);
        // 1/(z-w) = (dr, -di)/|d|^2 with dr = -wr
        const float p1 = -w.x * r1, p2 = -w.x * r2;
        const float q1 = -u1  * r1, q2 = -u2  * r2;
        const float Pp = p1 + p2, Pm = p1 - p2;
        const float Qp = q1 + q2, Qm = q2 - q1;
        // v/(z-w) + conj(v)/(z-conj(w)):
        //   re = vr*Pp + vi*Qm ; im = vr*Qp + vi*Pm
        float2 v;
        v = sv0[n]; aR0 += v.x*Pp + v.y*Qm; aI0 += v.x*Qp + v.y*Pm;
        v = sv1[n]; aR1 += v.x*Pp + v.y*Qm; aI1 += v.x*Qp + v.y*Pm;
        v = sv2[n]; aR2 += v.x*Pp + v.y*Qm; aI2 += v.x*Qp + v.y*Pm;
        v = sv3[n]; aR3 += v.x*Pp + v.y*Qm; aI3 += v.x*Qp + v.y*Pm;
    }

    const float dt = s_dt;
    const float r00r = aR0*dt, r00i = aI0*dt;
    const float r01r = aR1*dt, r01i = aI1*dt;
    const float r10r = aR2*dt, r10i = aI2*dt;
    const float r11r = aR3*dt, r11i = aI3*dt;

    // Woodbury: kf = r00 - r01*r10/(1+r11)
    const float dr = 1.0f + r11r, di = r11i;
    const float idn = __fdividef(1.0f, dr*dr + di*di);
    const float numr = r01r*r10r - r01i*r10i;
    const float numi = r01r*r10i + r01i*r10r;
    const float corr_r = (numr*dr + numi*di) * idn;
    const float corr_i = (numi*dr - numr*di) * idn;
    float kfr = r00r - corr_r;
    float kfi = r00i - corr_i;

    // multiply by 2/(1+omega) = 1 + i*tf
    const float outr = kfr - kfi * tf;
    const float outi = kfi + kfr * tf;
    g_kf[h * MM + m] = make_float2(outr, outi);
}

// ---------------------------------------------------------------------------
// Stage 2: irfft(k_f, n=2048) per h via real-packing + 1024-pt Stockham iFFT.
// One CTA per h, 512 threads, shared-memory ping-pong.
// ---------------------------------------------------------------------------
__global__ void __launch_bounds__(512)
irfft_kernel(float* __restrict__ out)
{
    __shared__ float2 sA[1024];
    __shared__ float2 sB[1024];

    const int h   = blockIdx.x;
    const int tid = threadIdx.x;
    const float2* __restrict__ K = &g_kf[h * MM];

    // Build Z'[m] = (E[m] + i*O[m]) / 1024,  m = 0..1023
    //   E  = (K[m] + conj(K[Nh-m]))/2
    //   O  = e^{+i*pi*m/1024} * (K[m] - conj(K[Nh-m]))/2
    // c2r semantics: imag of DC (m=0) and Nyquist (m=1024) ignored.
    #pragma unroll
    for (int r = 0; r < 2; r++) {
        const int m = tid + r * 512;
        float2 km = K[m];
        float2 kn = K[1024 - m];
        if (m == 0) { km.y = 0.f; kn.y = 0.f; }
        const float Ex = 0.5f * (km.x + kn.x);
        const float Ey = 0.5f * (km.y - kn.y);
        const float Ox = 0.5f * (km.x - kn.x);
        const float Oy = 0.5f * (km.y + kn.y);
        float s, c;
        sincospif((float)m * (1.0f / 1024.0f), &s, &c);
        const float Orx = Ox * c - Oy * s;
        const float Ory = Ox * s + Oy * c;
        const float scale = 1.0f / 1024.0f;
        sA[m] = make_float2((Ex - Ory) * scale, (Ey + Orx) * scale);
    }

    // 10 radix-2 Stockham stages (self-sorting), inverse sign (+).
    float2* src = sA;
    float2* dst = sB;
    int s_ = 1, ls = 0;
    for (int ncur = 1024; ncur >= 2; ncur >>= 1) {
        __syncthreads();
        const int mh = ncur >> 1;
        const int q  = tid & (s_ - 1);
        const int p  = tid >> ls;
        const float2 a = src[q + s_ * p];
        const float2 b = src[q + s_ * (p + mh)];
        const float2 sum = make_float2(a.x + b.x, a.y + b.y);
        const float2 dif = make_float2(a.x - b.x, a.y - b.y);
        float ws, wc;
        sincospif((float)(2 * p) / (float)ncur, &ws, &wc);  // e^{+2*pi*i*p/ncur}
        dst[q + s_ * 2 * p]       = sum;
        dst[q + s_ * (2 * p + 1)] = make_float2(dif.x * wc - dif.y * ws,
                                                dif.x * ws + dif.y * wc);
        float2* t = src; src = dst; dst = t;
        s_ <<= 1; ls++;
    }
    __syncthreads();

    // src == sA after 10 swaps; z[j] = x[2j] + i*x[2j+1]
    float2* o2 = (float2*)(out + (size_t)h * LEN);
    o2[tid]       = src[tid];
    o2[tid + 512] = src[tid + 512];
}

extern "C" void kernel_launch(void* const* d_in, const int* in_sizes, int n_in,
                              void* d_out, int out_size)
{
    const float* log_dt     = (const float*)d_in[0];
    const float* log_w_real = (const float*)d_in[1];
    const float* w_imag     = (const float*)d_in[2];
    const float* Bmat       = (const float*)d_in[3];
    const float* Cmat       = (const float*)d_in[4];
    const float* Pmat       = (const float*)d_in[5];
    float* out = (float*)d_out;

    dim3 g1(HDIM, (MM + 127) / 128);
    cauchy_kernel<<<g1, 128>>>(log_dt, log_w_real, w_imag, Bmat, Cmat, Pmat);
    irfft_kernel<<<HDIM, 512>>>(out);
}

// round 2
// speedup vs baseline: 1.7452x; 1.7452x over previous
#include <cuda_runtime.h>
#include <math.h>

#define HDIM 512
#define NN2 32
#define LEN 2048
#define MM 1025
#define KF_STRIDE 1028   // padded so (h*KF_STRIDE + 2*tid) is float4-aligned

typedef unsigned long long u64;

// scratch: half-spectrum k_f per h (complex), padded stride
__device__ float2 g_kf[HDIM * KF_STRIDE];

// ---- packed f32x2 helpers (sm_103a) --------------------------------------
__device__ __forceinline__ u64 pk2(float lo, float hi) {
    u64 r; asm("mov.b64 %0,{%1,%2};" : "=l"(r) : "f"(lo), "f"(hi)); return r;
}
__device__ __forceinline__ void upk2(u64 v, float& lo, float& hi) {
    asm("mov.b64 {%0,%1},%2;" : "=f"(lo), "=f"(hi) : "l"(v));
}
__device__ __forceinline__ u64 add2(u64 a, u64 b) {
    u64 r; asm("add.rn.f32x2 %0,%1,%2;" : "=l"(r) : "l"(a), "l"(b)); return r;
}
__device__ __forceinline__ u64 mul2(u64 a, u64 b) {
    u64 r; asm("mul.rn.f32x2 %0,%1,%2;" : "=l"(r) : "l"(a), "l"(b)); return r;
}
__device__ __forceinline__ u64 fma2(u64 a, u64 b, u64 c) {
    u64 r; asm("fma.rn.f32x2 %0,%1,%2,%3;" : "=l"(r) : "l"(a), "l"(b), "l"(c)); return r;
}

// Woodbury + bilinear post-factor for one m (r_ab already include dt)
__device__ __forceinline__ float2 wood(float R0, float I0, float R1, float I1,
                                       float R2, float I2, float R3, float I3,
                                       float t) {
    const float dr = 1.0f + R3, di = I3;
    const float idn = __fdividef(1.0f, dr*dr + di*di);
    const float numr = R1*R2 - I1*I2;
    const float numi = R1*I2 + I1*R2;
    const float cr = (numr*dr + numi*di) * idn;
    const float ci = (numi*dr - numr*di) * idn;
    const float kfr = R0 - cr, kfi = I0 - ci;
    return make_float2(kfr - kfi*t, kfi + kfr*t);   // * (1 + i t)
}

// ---------------------------------------------------------------------------
// Stage 1: Cauchy + Woodbury, conjugate pairs fused into one rational term:
//   v/(z-w) + conj(v)/(z-conj(w)) = (b + i a t) / (e + i f)
//   a = 4 Re v, b = -2 Re(v conj(w)), e = |w|^2 - 4t^2, f = -4 wr t,  z = 2it
// One block per h; thread tid<512 handles m = {2tid, 2tid+1} in one f32x2 lane;
// tid==512 handles m=1024 (t clamped to 1e8 -> converged asymptotic limit).
// ---------------------------------------------------------------------------
__global__ void __launch_bounds__(544)
cauchy_kernel(const float* __restrict__ log_dt,
              const float* __restrict__ log_w_real,
              const float* __restrict__ w_imag,
              const float* __restrict__ Bmat,
              const float* __restrict__ Cmat,
              const float* __restrict__ Pmat)
{
    __shared__ ulonglong2 s_cd[NN2];        // (c,c),(d,d)
    __shared__ ulonglong2 s_ab[4][NN2];     // (a,a),(b,b) per v-matrix (dt folded in)

    const int h   = blockIdx.x;
    const int tid = threadIdx.x;

    if (tid < NN2) {
        const int n   = tid;
        const int idx = h * NN2 + n;
        const float dt = expf(log_dt[h]);
        const float wr = -expf(log_w_real[idx]) * dt;
        const float wi = w_imag[idx] * dt;
        const float c  = wr*wr + wi*wi;
        const float d  = -4.0f * wr;

        const float Br = Bmat[2*idx], Bi = Bmat[2*idx+1];
        const float Cr = Cmat[2*idx], Ci = Cmat[2*idx+1];
        const float Pr = Pmat[2*idx], Pi = Pmat[2*idx+1];
        float vr[4], vi[4];
        vr[0] = Br*Cr - Bi*Ci;  vi[0] = Br*Ci + Bi*Cr;   // B*C
        vr[1] = Br*Pr + Bi*Pi;  vi[1] = Bi*Pr - Br*Pi;   // B*conj(P)
        vr[2] = Pr*Cr - Pi*Ci;  vi[2] = Pr*Ci + Pi*Cr;   // P*C
        vr[3] = Pr*Pr + Pi*Pi;  vi[3] = 0.0f;            // |P|^2

        s_cd[n] = make_ulonglong2(pk2(c, c), pk2(d, d));
        #pragma unroll
        for (int k = 0; k < 4; k++) {
            const float a =  4.0f * dt * vr[k];
            const float b = -2.0f * dt * (vr[k]*wr + vi[k]*wi);
            s_ab[k][n] = make_ulonglong2(pk2(a, a), pk2(b, b));
        }
    }
    __syncthreads();
    if (tid > 512) return;

    int m0, m1;
    if (tid < 512) { m0 = 2*tid; m1 = m0 + 1; } else { m0 = 1024; m1 = 1024; }

    float s0, c0, s1, c1;
    sincospif((float)m0 * (1.0f/2048.0f), &s0, &c0);
    sincospif((float)m1 * (1.0f/2048.0f), &s1, &c1);
    const float t0 = fminf(__fdividef(s0, c0), 1e8f);   // tan(pi m/L), Nyquist clamped
    const float t1 = fminf(__fdividef(s1, c1), 1e8f);

    const u64 tp  = pk2(t0, t1);
    const u64 tn  = pk2(-t0, -t1);
    const u64 t2n = pk2(-4.0f*t0*t0, -4.0f*t1*t1);

    u64 aR0=0, aR1=0, aR2=0, aR3=0;     // Re sums
    u64 aJ0=0, aJ1=0, aJ2=0, aJ3=0;     // -Im sums

    #pragma unroll 4
    for (int n = 0; n < NN2; n++) {
        const ulonglong2 cd = s_cd[n];
        const u64 e   = add2(cd.x, t2n);            // c - 4t^2
        const u64 f   = mul2(cd.y, tp);             // d*t
        const u64 mag = fma2(e, e, mul2(f, f));
        float mlo, mhi; upk2(mag, mlo, mhi);
        const u64 r   = pk2(__fdividef(1.0f, mlo), __fdividef(1.0f, mhi));
        const u64 er  = mul2(e, r);
        const u64 fr  = mul2(f, r);
        const u64 tfr  = mul2(tp, fr);
        const u64 nter = mul2(tn, er);              // -t*e*r
        ulonglong2 ab;
        // Re += b*er + a*tfr ;  (-Im) += b*fr + a*(-t*er)
        ab = s_ab[0][n];
        aR0 = fma2(ab.x, tfr,  fma2(ab.y, er, aR0));
        aJ0 = fma2(ab.x, nter, fma2(ab.y, fr, aJ0));
        ab = s_ab[1][n];
        aR1 = fma2(ab.x, tfr,  fma2(ab.y, er, aR1));
        aJ1 = fma2(ab.x, nter, fma2(ab.y, fr, aJ1));
        ab = s_ab[2][n];
        aR2 = fma2(ab.x, tfr,  fma2(ab.y, er, aR2));
        aJ2 = fma2(ab.x, nter, fma2(ab.y, fr, aJ2));
        ab = s_ab[3][n];
        aR3 = fma2(ab.x, tfr,  fma2(ab.y, er, aR3));
        aJ3 = fma2(ab.x, nter, fma2(ab.y, fr, aJ3));
    }

    float R0l,R0h,R1l,R1h,R2l,R2h,R3l,R3h;
    float J0l,J0h,J1l,J1h,J2l,J2h,J3l,J3h;
    upk2(aR0,R0l,R0h); upk2(aR1,R1l,R1h); upk2(aR2,R2l,R2h); upk2(aR3,R3l,R3h);
    upk2(aJ0,J0l,J0h); upk2(aJ1,J1l,J1h); upk2(aJ2,J2l,J2h); upk2(aJ3,J3l,J3h);

    const float2 o0 = wood(R0l,-J0l, R1l,-J1l, R2l,-J2l, R3l,-J3l, t0);

    if (tid < 512) {
        const float2 o1 = wood(R0h,-J0h, R1h,-J1h, R2h,-J2h, R3h,-J3h, t1);
        float4* dst = (float4*)&g_kf[h*KF_STRIDE + 2*tid];
        *dst = make_float4(o0.x, o0.y, o1.x, o1.y);
    } else {
        g_kf[h*KF_STRIDE + 1024] = o0;
    }
}

// ---------------------------------------------------------------------------
// Stage 2: irfft(k_f, 2048) per h via real-packing + 1024-pt Stockham iFFT.
// Twiddles from a shared table (1 sincospif at init instead of 10 per thread).
// ---------------------------------------------------------------------------
__global__ void __launch_bounds__(512)
irfft_kernel(float* __restrict__ out)
{
    __shared__ float2 sA[1024];
    __shared__ float2 sB[1024];
    __shared__ float2 tw[512];      // tw[j] = e^{+2*pi*i*j/1024}

    const int h   = blockIdx.x;
    const int tid = threadIdx.x;
    const float2* __restrict__ K = &g_kf[h * KF_STRIDE];

    { float s, c; sincospif((float)tid * (1.0f/512.0f), &s, &c); tw[tid] = make_float2(c, s); }

    // Z'[m] = (E[m] + i*O[m]) / 1024  (real-packing of the c2r transform)
    #pragma unroll
    for (int r = 0; r < 2; r++) {
        const int m = tid + r * 512;
        float2 km = K[m];
        float2 kn = K[1024 - m];
        if (m == 0) { km.y = 0.f; kn.y = 0.f; }
        const float Ex = 0.5f * (km.x + kn.x);
        const float Ey = 0.5f * (km.y - kn.y);
        const float Ox = 0.5f * (km.x - kn.x);
        const float Oy = 0.5f * (km.y + kn.y);
        float s, c;
        sincospif((float)m * (1.0f / 1024.0f), &s, &c);
        const float Orx = Ox * c - Oy * s;
        const float Ory = Ox * s + Oy * c;
        const float scale = 1.0f / 1024.0f;
        sA[m] = make_float2((Ex - Ory) * scale, (Ey + Orx) * scale);
    }

    // 10 radix-2 Stockham stages (self-sorting), inverse sign (+)
    float2* src = sA;
    float2* dst = sB;
    int s_ = 1, ls = 0;
    for (int ncur = 1024; ncur >= 2; ncur >>= 1) {
        __syncthreads();
        const int mh = ncur >> 1;
        const int q  = tid & (s_ - 1);
        const int p  = tid >> ls;
        const float2 a = src[q + s_ * p];
        const float2 b = src[q + s_ * (p + mh)];
        const float2 sum = make_float2(a.x + b.x, a.y + b.y);
        const float2 dif = make_float2(a.x - b.x, a.y - b.y);
        const float2 w = tw[p << ls];               // e^{+2*pi*i*p/ncur}
        dst[q + s_ * 2 * p]       = sum;
        dst[q + s_ * (2 * p + 1)] = make_float2(dif.x * w.x - dif.y * w.y,
                                                dif.x * w.y + dif.y * w.x);
        float2* t = src; src = dst; dst = t;
        s_ <<= 1; ls++;
    }
    __syncthreads();

    // src == sA after 10 swaps; z[j] = x[2j] + i*x[2j+1]
    float2* o2 = (float2*)(out + (size_t)h * LEN);
    o2[tid]       = src[tid];
    o2[tid + 512] = src[tid + 512];
}

extern "C" void kernel_launch(void* const* d_in, const int* in_sizes, int n_in,
                              void* d_out, int out_size)
{
    const float* log_dt     = (const float*)d_in[0];
    const float* log_w_real = (const float*)d_in[1];
    const float* w_imag     = (const float*)d_in[2];
    const float* Bmat       = (const float*)d_in[3];
    const float* Cmat       = (const float*)d_in[4];
    const float* Pmat       = (const float*)d_in[5];
    float* out = (float*)d_out;

    cauchy_kernel<<<HDIM, 544>>>(log_dt, log_w_real, w_imag, Bmat, Cmat, Pmat);
    irfft_kernel<<<HDIM, 512>>>(out);
}